// round 12
// baseline (speedup 1.0000x reference)
#include <cuda_runtime.h>

#define Bx 2
#define Nx 32
#define Cx 128
#define Px 8192
#define NB 64
#define G3x 8
#define NEGV (-1e30f)
#define GRIDX 592            // 148 SMs x 4 CTAs: exact wave-1 fill, zero imbalance
#define NTILES 2048          // 32x32 transpose tiles
#define NTASK 512            // (box,bin) tasks

// Scratch (static device globals — allowed)
__device__ float    g_featT[(size_t)Bx * Px * Cx];  // transposed features [b][p][c]
__device__ int      g_idx[NB * Px];                 // per-box per-segment compacted lists
__device__ int      g_segcnt[NB * 8];               // per-box per-segment counts
__device__ unsigned g_bar = 0;                      // grid-barrier ticket counter

// ---------------------------------------------------------------------------
// Persistent kernel, 592 CTAs (4 per SM exactly -> balanced LTS load).
//  Pre-barrier: CTA g transposes tiles {g + 592*i} (3-4 each, offset-skip),
//    and (g<512) compacts segment g&7 of box g>>3. All global loads issued
//    before the single work sync.
//  Grid barrier: release fence (all threads) -> sync -> t0 ticket+spin ->
//    acquire fence -> sync.
//  Post-barrier (g<512): assemble bin's rank range from the 8 segment lists,
//    coalesced float4 gather-max over featT.
// ---------------------------------------------------------------------------
__global__ void __launch_bounds__(256, 4) roipool_fused_kernel(
    const float* __restrict__ feat,    // [B][C][P]
    const float* __restrict__ boxes,   // [B][N][6]
    const int*   __restrict__ offset,  // [B]
    const float* __restrict__ pc,      // [B][P][3]
    float*       __restrict__ out)     // [B][N][C][8]
{
    __shared__ __align__(16) float s_tile[4][32][33];
    __shared__ int   s_wcnt[8];
    __shared__ int   s_bin[1032];
    __shared__ __align__(16) float s_red[8][128];

    const int g    = blockIdx.x;
    const int t    = threadIdx.x;
    const int lane = t & 31;
    const int w    = t >> 5;
    const bool have = (g < NTASK);     // uniform per CTA
    const int bn   = g >> 3;           // box (valid iff have)
    const int k    = g & 7;            // bin == segment
    const int bb   = bn >> 5;          // batch of this box

    const int off0 = __ldg(offset + 0);
    const int off1 = __ldg(offset + 1);

    // ---- transpose tiles: ids {g + 592*i}, decoded per tile ----
    const int tx = t & 7, ty = t >> 3;
    bool   keep[4];
    int    pb[4], cb[4], btl[4];
    float4 v[4];
#pragma unroll
    for (int i = 0; i < 4; i++) {
        const int id = g + GRIDX * i;
        keep[i] = false;
        if (id < NTILES) {
            pb[i]  = (id & 255) * 32;
            cb[i]  = ((id >> 8) & 3) * 32;
            btl[i] = id >> 10;
            const int offt = btl[i] ? off1 : off0;
            if (pb[i] < offt) {                      // rows never referenced -> skip
                keep[i] = true;
                v[i] = *(const float4*)(feat + (size_t)btl[i] * Cx * Px
                                        + (size_t)(cb[i] + ty) * Px + pb[i] + tx * 4);
            }
        }
    }

    // ---- box params (uniform __ldg broadcast; RO inputs) ----
    float lox = 0, hix = 0, loy = 0, hiy = 0, loz = 0, hiz = 0;
    if (have) {
        const float bx0 = __ldg(boxes + bn * 6 + 0);
        const float by0 = __ldg(boxes + bn * 6 + 1);
        const float bz0 = __ldg(boxes + bn * 6 + 2);
        const float hx  = __ldg(boxes + bn * 6 + 3) * 0.5f;
        const float hy  = __ldg(boxes + bn * 6 + 4) * 0.5f;
        const float hz  = __ldg(boxes + bn * 6 + 5) * 0.5f;
        lox = bx0 - hx; hix = bx0 + hx;
        loy = by0 - hy; hiy = by0 + hy;
        loz = bz0 - hz; hiz = bz0 + hz;
    }

    // ---- pc loads for segment k (overlap transpose latency) ----
    const int offb = bb ? off1 : off0;
    const float* pcb = pc + (size_t)bb * Px * 3;
    const int wseg = k * 1024 + w * 128;             // this warp's 128 points

    float qx[4], qy[4], qz[4];
#pragma unroll
    for (int i = 0; i < 4; i++) {
        const int p = wseg + i * 32 + lane;
        if (have && p < offb) {
            qx[i] = __ldg(pcb + p * 3 + 0);
            qy[i] = __ldg(pcb + p * 3 + 1);
            qz[i] = __ldg(pcb + p * 3 + 2);
        }
    }

    // ---- STS tiles ----
#pragma unroll
    for (int i = 0; i < 4; i++) {
        if (keep[i]) {
            s_tile[i][ty][tx * 4 + 0] = v[i].x;
            s_tile[i][ty][tx * 4 + 1] = v[i].y;
            s_tile[i][ty][tx * 4 + 2] = v[i].z;
            s_tile[i][ty][tx * 4 + 3] = v[i].w;
        }
    }

    // ---- flags + ballots (flag=false for !have: ballots uniform) ----
    unsigned bal[4];
    unsigned fl = 0;
    int cntw = 0;
#pragma unroll
    for (int i = 0; i < 4; i++) {
        const int p = wseg + i * 32 + lane;
        bool flag = false;
        if (have && p < offb)
            flag = (qx[i] >= lox) & (qx[i] <= hix) &
                   (qy[i] >= loy) & (qy[i] <= hiy) &
                   (qz[i] >= loz) & (qz[i] <= hiz);
        bal[i] = __ballot_sync(0xffffffffu, flag);
        fl |= ((unsigned)flag) << i;
        cntw += __popc(bal[i]);
    }
    if (lane == 0) s_wcnt[w] = cntw;

    __syncthreads();                                 // single work-section sync

    // ---- featT stores ----
    {
        const int cx = t & 7, py = t >> 3;
#pragma unroll
        for (int i = 0; i < 4; i++) {
            if (keep[i]) {
                float4 o;
                o.x = s_tile[i][cx * 4 + 0][py];
                o.y = s_tile[i][cx * 4 + 1][py];
                o.z = s_tile[i][cx * 4 + 2][py];
                o.w = s_tile[i][cx * 4 + 3][py];
                *(float4*)(g_featT + (size_t)btl[i] * Px * Cx
                           + (size_t)(pb[i] + py) * Cx + cb[i] + cx * 4) = o;
            }
        }
    }

    // ---- ordered segment-local compaction writes ----
    if (have) {
        int base = 0, tot = 0;
#pragma unroll
        for (int ww = 0; ww < 8; ww++) {
            if (ww < w) base += s_wcnt[ww];
            tot += s_wcnt[ww];
        }
        int* gi = g_idx + bn * Px + k * 1024;
#pragma unroll
        for (int i = 0; i < 4; i++) {
            if ((fl >> i) & 1u)
                gi[base + __popc(bal[i] & ((1u << lane) - 1u))] = wseg + i * 32 + lane;
            base += __popc(bal[i]);
        }
        if (t == 0) g_segcnt[bn * 8 + k] = tot;
    }

    // ---- grid barrier: release/acquire ----
    __threadfence();           // RELEASE: each thread publishes its own stores
    __syncthreads();           // all fences done before arrival
    if (t == 0) {
        const unsigned a = atomicAdd(&g_bar, 1u);
        const unsigned target = (a / GRIDX + 1u) * GRIDX;
        volatile unsigned* vb = &g_bar;
        unsigned ns = 32;
        while (*vb < target) { __nanosleep(ns); if (ns < 256) ns <<= 1; }
        __threadfence();       // ACQUIRE
    }
    __syncthreads();

    if (!have) return;         // idle bins exit; only intra-CTA syncs remain

    // ---- assemble bin k's index list (plain coherent loads) ----
    int c[8];
#pragma unroll
    for (int s = 0; s < 8; s++) c[s] = g_segcnt[bn * 8 + s];
    int cnt = 0;
#pragma unroll
    for (int s = 0; s < 8; s++) cnt += c[s];

    const int st = (k * cnt) >> 3;                   // floor(k*cnt/8)
    const int en = ((k + 1) * cnt + 7) >> 3;         // ceil((k+1)*cnt/8)
    const int nb = en - st;                          // == 0 iff cnt == 0

    for (int j = t; j < nb; j += 256) {
        const int r = st + j;                        // global rank in this box
        int acc = 0, seg = 0, loc = 0;
#pragma unroll
        for (int s = 0; s < 8; s++) {
            const int nxt = acc + c[s];
            if (r >= acc && r < nxt) { seg = s; loc = r - acc; }
            acc = nxt;
        }
        s_bin[j] = g_idx[bn * Px + seg * 1024 + loc];
    }
    __syncthreads();

    // ---- gather max: 8 warps over points, lane = float4 channel group ----
    const float4* ftb = (const float4*)(g_featT + (size_t)bb * Px * Cx);
    float4 m = make_float4(NEGV, NEGV, NEGV, NEGV);
    for (int j = w; j < nb; j += 32) {               // batch-4 for MLP
        const int q0 = s_bin[j];
        const int q1 = (j + 8  < nb) ? s_bin[j + 8]  : q0;
        const int q2 = (j + 16 < nb) ? s_bin[j + 16] : q0;
        const int q3 = (j + 24 < nb) ? s_bin[j + 24] : q0;
        const float4 v0 = ftb[(size_t)q0 * 32 + lane];
        const float4 v1 = ftb[(size_t)q1 * 32 + lane];
        const float4 v2 = ftb[(size_t)q2 * 32 + lane];
        const float4 v3 = ftb[(size_t)q3 * 32 + lane];
        m.x = fmaxf(fmaxf(m.x, v0.x), fmaxf(fmaxf(v1.x, v2.x), v3.x));
        m.y = fmaxf(fmaxf(m.y, v0.y), fmaxf(fmaxf(v1.y, v2.y), v3.y));
        m.z = fmaxf(fmaxf(m.z, v0.z), fmaxf(fmaxf(v1.z, v2.z), v3.z));
        m.w = fmaxf(fmaxf(m.w, v0.w), fmaxf(fmaxf(v1.w, v2.w), v3.w));
    }
    *(float4*)&s_red[w][lane * 4] = m;
    __syncthreads();

    if (t < 128) {
        float r = s_red[0][t];
#pragma unroll
        for (int ww = 1; ww < 8; ww++) r = fmaxf(r, s_red[ww][t]);
        out[((size_t)bn * Cx + t) * G3x + k] = (cnt > 0) ? r : 0.0f;
    }
}

// ---------------------------------------------------------------------------
// Harness entry — single launch
// ---------------------------------------------------------------------------
extern "C" void kernel_launch(void* const* d_in, const int* in_sizes, int n_in,
                              void* d_out, int out_size)
{
    const float* boxes  = (const float*)d_in[0];   // (B, N, 6)
    const float* feat   = (const float*)d_in[1];   // (B, C, P)
    const int*   offset = (const int*)  d_in[2];   // (B,)
    const float* pc     = (const float*)d_in[3];   // (B, P, 3)
    float*       out    = (float*)d_out;           // (B, N, C, 2, 2, 2)

    roipool_fused_kernel<<<GRIDX, 256>>>(feat, boxes, offset, pc, out);
}